// round 8
// baseline (speedup 1.0000x reference)
#include <cuda_runtime.h>

#define N_REL   200
#define BATCH   16384
#define DIM     128
#define N_ENT   500000
#define TILE    4
#define NBLOCKS 296
#define THREADS 512
#define MAXT    24

// Scratch (static __device__ globals — no allocation allowed)
__device__ int          g_cnt[N_REL];          // zero at start; reset by last block
__device__ int          g_list[N_REL * BATCH];
__device__ float        g_part[NBLOCKS];
__device__ unsigned int g_done;                // zero-init; reset by last block

typedef unsigned long long ull;

// ---- packed f32x2 helpers (pos/neg bilinears share one issue slot) ----
__device__ __forceinline__ ull ffma2(ull a, ull b, ull c) {
    ull d;
    asm("fma.rn.f32x2 %0, %1, %2, %3;" : "=l"(d) : "l"(a), "l"(b), "l"(c));
    return d;
}
__device__ __forceinline__ ull mul2(ull a, ull b) {
    ull d;
    asm("mul.rn.f32x2 %0, %1, %2;" : "=l"(d) : "l"(a), "l"(b));
    return d;
}
__device__ __forceinline__ ull dup2(float x) {
    ull d; unsigned int xi = __float_as_uint(x);
    asm("mov.b64 %0, {%1, %2};" : "=l"(d) : "r"(xi), "r"(xi));
    return d;
}

// ---- cp.async helpers ----
__device__ __forceinline__ void cp4(void* dst, const void* src) {
    unsigned sa = (unsigned)__cvta_generic_to_shared(dst);
    asm volatile("cp.async.ca.shared.global [%0], [%1], 4;" :: "r"(sa), "l"(src));
}
__device__ __forceinline__ void cp_commit() {
    asm volatile("cp.async.commit_group;" ::: "memory");
}
__device__ __forceinline__ void cp_wait1() {
    asm volatile("cp.async.wait_group 1;" ::: "memory");
}
__device__ __forceinline__ void cp_wait0() {
    asm volatile("cp.async.wait_group 0;" ::: "memory");
}

// Detect int64-vs-int32 index dtype from first 32 elements.
__device__ __forceinline__ int detect_is64(const void* data) {
    const unsigned int* w = (const unsigned int*)data;
    unsigned int acc = 0;
    #pragma unroll
    for (int k = 0; k < 32; k++) acc |= w[2 * k + 1];
    return (acc == 0) ? 1 : 0;   // true int64 (<2^31) => odd words all zero
}

// Read data[elem] under either index dtype, with defensive clamping.
__device__ __forceinline__ int read_idx(const void* data, int elem, int is64, int limit) {
    long long v;
    if (is64) v = ((const long long*)data)[elem];
    else      v = ((const int*)data)[elem];
    if (v < 0) v = 0;
    if (v >= limit) v = limit - 1;
    return (int)v;
}

// Bucket batch elements by relation id (g_cnt zero on entry; reset each launch
// by rescal's last block).
__global__ void build_kernel(const void* __restrict__ data) {
    __shared__ int s_is64;
    int tid = threadIdx.x;
    if (tid == 0) s_is64 = detect_is64(data);
    __syncthreads();
    int b = blockIdx.x * THREADS + tid;
    if (b < BATCH) {
        int r = read_idx(data, b * 5 + 2, s_is64, N_REL);
        int p = atomicAdd(&g_cnt[r], 1);
        g_list[r * BATCH + p] = b;
    }
}

struct __align__(16) Buf {
    float2 h[TILE][DIM];   // (h, ch)
    float2 t[TILE][DIM];   // (t, ct)
};

// Async gather for one tile (2048 floats, 4 cp.async/thread).
__device__ __forceinline__ void issue_gather(
    Buf* buf, const int (*ids)[4], const float* __restrict__ ent, int tid)
{
    #pragma unroll
    for (int i = 0; i < 4; i++) {
        int flat = i * THREADS + tid;      // 0..2047
        int e = flat >> 9;                 // element 0..3
        int v = (flat >> 7) & 3;           // 0:h 1:t 2:ch 3:ct
        int k = flat & 127;
        const float* src = ent + (size_t)ids[e][v] * DIM + k;
        float2* base = (v == 0 || v == 2) ? &buf->h[e][k] : &buf->t[e][k];
        float*  dst  = (v == 0 || v == 1) ? &base->x : &base->y;
        cp4(dst, src);
    }
    cp_commit();
}

// Persistent: 296 blocks x 512 threads (2 blocks/SM -> 32 warps resident).
// Thread = (jpair = tid&63 ; rowe = tid>>6). One barrier per tile; the
// cross-warp combine for tile j-1 runs on a rotating warp concurrently with
// tile j's FFMA work (wsum double-buffered).
__global__ __launch_bounds__(THREADS, 2) void rescal_kernel(
    const void*  __restrict__ data,
    const float* __restrict__ ent,
    const float* __restrict__ rel,
    float*       __restrict__ out)
{
    __shared__ Buf   s_buf[2];
    __shared__ int   s_toff[N_REL];
    __shared__ int   s_ws[8], s_winc[8];
    __shared__ int   s_nt, s_is64;
    __shared__ int   st_r[MAXT], st_s[MAXT], st_n[MAXT];
    __shared__ int   s_ids[MAXT][TILE][4];
    __shared__ float wsum[2][TILE][16];
    __shared__ float s_part[16];
    __shared__ int   s_last;

    const int tid  = threadIdx.x;
    const int jp   = tid & 63;            // column pair: j = 2jp, 2jp+1
    const int rowe = tid >> 6;            // row eighth: k in [rowe*16, +16)
    const int lane = tid & 31;
    const int wid  = tid >> 5;            // 0..15

    if (tid == 0) s_is64 = detect_is64(data);

    // ---- tile-offset scan over g_cnt (shuffle scan, warps 0..7) ----
    int tc = 0, incl = 0;
    if (tid < 256) {
        tc = (tid < N_REL) ? (g_cnt[tid] + TILE - 1) / TILE : 0;
        int v = tc;
        #pragma unroll
        for (int o = 1; o < 32; o <<= 1) {
            int u = __shfl_up_sync(0xffffffffu, v, o);
            if (lane >= o) v += u;
        }
        if (lane == 31) s_ws[wid] = v;
        incl = v;
    }
    __syncthreads();
    if (wid == 0) {
        int x = (lane < 8) ? s_ws[lane] : 0;
        #pragma unroll
        for (int o = 1; o < 8; o <<= 1) {
            int u = __shfl_up_sync(0xffffffffu, x, o);
            if (lane >= o) x += u;
        }
        if (lane < 8) s_winc[lane] = x;
    }
    __syncthreads();
    if (tid < 256) {
        int base = (wid == 0) ? 0 : s_winc[wid - 1];
        incl += base;
        if (tid < N_REL) s_toff[tid] = incl - tc;  // exclusive prefix
        if (tid == N_REL - 1) s_nt = incl;
    }
    __syncthreads();

    const int nt  = s_nt;
    const int t0  = (int)((long long)blockIdx.x * nt / NBLOCKS);
    const int t1  = (int)((long long)(blockIdx.x + 1) * nt / NBLOCKS);
    const int ntb = t1 - t0;
    const int is64 = s_is64;

    // ---- per-tile metadata: binary search for relation ----
    if (tid < ntb) {
        int t = t0 + tid;
        int lo = 0, hi = N_REL;
        while (hi - lo > 1) {
            int m = (lo + hi) >> 1;
            if (s_toff[m] <= t) lo = m; else hi = m;
        }
        int s0 = (t - s_toff[lo]) * TILE;
        int nv = g_cnt[lo] - s0;
        st_r[tid] = lo;
        st_s[tid] = s0;
        st_n[tid] = (nv > TILE) ? TILE : nv;
    }
    __syncthreads();

    // ---- prefetch all entity ids for this block's tiles ----
    if (tid < ntb * TILE) {
        int tt = tid >> 2, e = tid & 3;
        int nv = st_n[tt];
        int b  = g_list[st_r[tt] * BATCH + st_s[tt] + ((e < nv) ? e : 0)];
        s_ids[tt][e][0] = read_idx(data, b * 5 + 0, is64, N_ENT);  // h
        s_ids[tt][e][1] = read_idx(data, b * 5 + 1, is64, N_ENT);  // t
        s_ids[tt][e][2] = read_idx(data, b * 5 + 3, is64, N_ENT);  // ch
        s_ids[tt][e][3] = read_idx(data, b * 5 + 4, is64, N_ENT);  // ct
    }
    __syncthreads();

    float2 Rreg[16];                       // R[rowe*16+kk][2jp .. 2jp+1]
    int    cur_r = -1;
    float  blockAcc = 0.0f;                // on lanes 0,16 of every warp

    if (ntb > 0) issue_gather(&s_buf[0], s_ids[0], ent, tid);

    for (int j = 0; j < ntb; j++) {
        if (j + 1 < ntb)
            issue_gather(&s_buf[(j + 1) & 1], s_ids[j + 1], ent, tid);

        const int r = st_r[j];
        if (r != cur_r) {                  // reload R block (L2-hot, coalesced)
            const float* Rp = rel + (size_t)r * (DIM * DIM)
                                  + (size_t)(rowe * 16) * DIM + jp * 2;
            #pragma unroll
            for (int kk = 0; kk < 16; kk++)
                Rreg[kk] = __ldg((const float2*)(Rp + (size_t)kk * DIM));
            cur_r = r;
        }

        if (j + 1 < ntb) cp_wait1(); else cp_wait0();
        __syncthreads();   // buf[j] ready AND wsum[(j-1)&1] fully written

        // Rotating warp combines tile j-1 while the rest start tile j's FMA.
        if (j > 0 && wid == ((j - 1) & 15)) {
            const int   pb = (j - 1) & 1;
            const int   nv = st_n[j - 1];
            const int   half = lane >> 4;  // 0/1
            const int   wl   = lane & 15;
            float v1 = wsum[pb][half][wl];
            float v2 = wsum[pb][2 + half][wl];
            #pragma unroll
            for (int o = 8; o; o >>= 1) {
                v1 += __shfl_xor_sync(0xffffffffu, v1, o);
                v2 += __shfl_xor_sync(0xffffffffu, v2, o);
            }
            if (wl == 0) {                 // lanes 0 and 16
                if (half < nv) {
                    float s = v1 + 1.0f;
                    if (s > 0.0f) blockAcc += s * (1.0f / BATCH);
                }
                if (2 + half < nv) {
                    float s = v2 + 1.0f;
                    if (s > 0.0f) blockAcc += s * (1.0f / BATCH);
                }
            }
        }

        const Buf* buf = &s_buf[j & 1];
        const int  kb  = rowe * 16;
        const int  cb  = j & 1;

        ull acc0[TILE], acc1[TILE];        // (pos,neg) for j0 and j1
        #pragma unroll
        for (int e = 0; e < TILE; e++) { acc0[e] = 0ull; acc1[e] = 0ull; }

        #pragma unroll
        for (int kk = 0; kk < 16; kk += 2) {
            ull b00 = dup2(Rreg[kk].x);
            ull b01 = dup2(Rreg[kk].y);
            ull b10 = dup2(Rreg[kk + 1].x);
            ull b11 = dup2(Rreg[kk + 1].y);
            #pragma unroll
            for (int e = 0; e < TILE; e++) {
                ulonglong2 hv = *reinterpret_cast<const ulonglong2*>(&buf->h[e][kb + kk]);
                acc0[e] = ffma2(hv.x, b00, acc0[e]);
                acc1[e] = ffma2(hv.x, b01, acc1[e]);
                acc0[e] = ffma2(hv.y, b10, acc0[e]);
                acc1[e] = ffma2(hv.y, b11, acc1[e]);
            }
        }

        // contrib_e = sum_j accp*t[j] - accn*ct[j]; per-warp reduce
        #pragma unroll
        for (int e = 0; e < TILE; e++) {
            ulonglong2 tv = *reinterpret_cast<const ulonglong2*>(&buf->t[e][jp * 2]);
            ull p = mul2(acc0[e], tv.x);
            ull q = mul2(acc1[e], tv.y);
            float c = (__uint_as_float((unsigned int)p)
                     - __uint_as_float((unsigned int)(p >> 32)))
                    + (__uint_as_float((unsigned int)q)
                     - __uint_as_float((unsigned int)(q >> 32)));
            #pragma unroll
            for (int o = 16; o; o >>= 1)
                c += __shfl_xor_sync(0xffffffffu, c, o);
            if (lane == 0) wsum[cb][e][wid] = c;
        }
        // no barrier here: next loop iteration's barrier publishes wsum[cb]
    }

    // ---- tail: combine the last tile ----
    __syncthreads();
    if (ntb > 0 && wid == ((ntb - 1) & 15)) {
        const int pb = (ntb - 1) & 1;
        const int nv = st_n[ntb - 1];
        const int half = lane >> 4;
        const int wl   = lane & 15;
        float v1 = wsum[pb][half][wl];
        float v2 = wsum[pb][2 + half][wl];
        #pragma unroll
        for (int o = 8; o; o >>= 1) {
            v1 += __shfl_xor_sync(0xffffffffu, v1, o);
            v2 += __shfl_xor_sync(0xffffffffu, v2, o);
        }
        if (wl == 0) {
            if (half < nv) {
                float s = v1 + 1.0f;
                if (s > 0.0f) blockAcc += s * (1.0f / BATCH);
            }
            if (2 + half < nv) {
                float s = v2 + 1.0f;
                if (s > 0.0f) blockAcc += s * (1.0f / BATCH);
            }
        }
    }

    // ---- block partial (blockAcc on lanes 0,16 of each warp) ----
    blockAcc += __shfl_xor_sync(0xffffffffu, blockAcc, 16);
    if (lane == 0) s_part[wid] = blockAcc;
    __syncthreads();
    if (tid == 0) {
        float total = 0.0f;
        #pragma unroll
        for (int w = 0; w < 16; w++) total += s_part[w];
        g_part[blockIdx.x] = total;
        __threadfence();
        unsigned int old = atomicAdd(&g_done, 1u);
        s_last = (old == NBLOCKS - 1) ? 1 : 0;
    }
    __syncthreads();
    if (s_last) {
        __threadfence();
        float v = (tid < NBLOCKS) ? g_part[tid] : 0.0f;
        #pragma unroll
        for (int o = 16; o; o >>= 1)
            v += __shfl_xor_sync(0xffffffffu, v, o);
        if (lane == 0) s_part[wid] = v;
        __syncthreads();
        if (wid == 0) {
            float x = (lane < 16) ? s_part[lane] : 0.0f;
            #pragma unroll
            for (int o = 8; o; o >>= 1)
                x += __shfl_xor_sync(0xffffffffu, x, o);
            if (lane == 0) out[0] = x;
        }
        // reset state for next graph replay
        if (tid < N_REL) g_cnt[tid] = 0;
        if (tid == 0)    g_done = 0u;
    }
}

extern "C" void kernel_launch(void* const* d_in, const int* in_sizes, int n_in,
                              void* d_out, int out_size) {
    const void*  data = d_in[0];
    const float* ent  = (const float*)d_in[1];
    const float* rel  = (const float*)d_in[2];
    float*       out  = (float*)d_out;

    build_kernel<<<(BATCH + THREADS - 1) / THREADS, THREADS>>>(data);
    rescal_kernel<<<NBLOCKS, THREADS>>>(data, ent, rel, out);
}

// round 9
// speedup vs baseline: 1.4224x; 1.4224x over previous
#include <cuda_runtime.h>

#define N_REL   200
#define BATCH   16384
#define DIM     128
#define N_ENT   500000
#define TILE    8
#define NBLOCKS 296
#define THREADS 512
#define MAXT    12
#define APAD    132   // row pitch (floats): 132 mod 32 = 4 -> conflict-free frags

// Scratch (static __device__ globals — no allocation allowed)
__device__ int          g_cnt[N_REL];          // zero at start; reset by last block
__device__ int          g_list[N_REL * BATCH];
__device__ float        g_part[NBLOCKS];
__device__ unsigned int g_done;                // zero-init; reset by last block

// ---- tf32 warp MMA: D(16x8) += A(16x8) * B(8x8) ----
__device__ __forceinline__ void mma_tf32(float c[4],
                                         unsigned a0, unsigned a1,
                                         unsigned a2, unsigned a3,
                                         unsigned b0, unsigned b1) {
    asm volatile(
        "mma.sync.aligned.m16n8k8.row.col.f32.tf32.tf32.f32 "
        "{%0,%1,%2,%3}, {%4,%5,%6,%7}, {%8,%9}, {%0,%1,%2,%3};"
        : "+f"(c[0]), "+f"(c[1]), "+f"(c[2]), "+f"(c[3])
        : "r"(a0), "r"(a1), "r"(a2), "r"(a3), "r"(b0), "r"(b1));
}

// ---- cp.async helpers ----
__device__ __forceinline__ void cp4(void* dst, const void* src) {
    unsigned sa = (unsigned)__cvta_generic_to_shared(dst);
    asm volatile("cp.async.ca.shared.global [%0], [%1], 4;" :: "r"(sa), "l"(src));
}
__device__ __forceinline__ void cp_commit() {
    asm volatile("cp.async.commit_group;" ::: "memory");
}
__device__ __forceinline__ void cp_wait1() {
    asm volatile("cp.async.wait_group 1;" ::: "memory");
}
__device__ __forceinline__ void cp_wait0() {
    asm volatile("cp.async.wait_group 0;" ::: "memory");
}

// Detect int64-vs-int32 index dtype from first 32 elements.
__device__ __forceinline__ int detect_is64(const void* data) {
    const unsigned int* w = (const unsigned int*)data;
    unsigned int acc = 0;
    #pragma unroll
    for (int k = 0; k < 32; k++) acc |= w[2 * k + 1];
    return (acc == 0) ? 1 : 0;   // true int64 (<2^31) => odd words all zero
}

// Read data[elem] under either index dtype, with defensive clamping.
__device__ __forceinline__ int read_idx(const void* data, int elem, int is64, int limit) {
    long long v;
    if (is64) v = ((const long long*)data)[elem];
    else      v = ((const int*)data)[elem];
    if (v < 0) v = 0;
    if (v >= limit) v = limit - 1;
    return (int)v;
}

// Bucket batch elements by relation id.
__global__ void build_kernel(const void* __restrict__ data) {
    __shared__ int s_is64;
    int tid = threadIdx.x;
    if (tid == 0) s_is64 = detect_is64(data);
    __syncthreads();
    int b = blockIdx.x * THREADS + tid;
    if (b < BATCH) {
        int r = read_idx(data, b * 5 + 2, s_is64, N_REL);
        int p = atomicAdd(&g_cnt[r], 1);
        g_list[r * BATCH + p] = b;
    }
}

struct __align__(16) Buf {
    float A[16][APAD];   // rows 0-7: h[e], rows 8-15: ch[e]
    float T[16][APAD];   // rows 0-7: t[e], rows 8-15: ct[e]
};

// Async gather for one tile: 32 entity vectors (4096 floats), 8 cp.async/thread.
__device__ __forceinline__ void issue_gather(
    Buf* buf, const int (*ids)[4], const float* __restrict__ ent, int tid)
{
    #pragma unroll
    for (int i = 0; i < 8; i++) {
        int flat = i * THREADS + tid;      // 0..4095
        int vec  = flat >> 7;              // 0..31
        int k    = flat & 127;
        int e    = vec & 7;
        float* dst;
        int id;
        if (vec < 16) {                    // A: h (vec<8) or ch
            id  = ids[e][(vec < 8) ? 0 : 2];
            dst = &buf->A[vec][k];
        } else {                           // T: t (vec<24) or ct
            id  = ids[e][(vec < 24) ? 1 : 3];
            dst = &buf->T[vec - 16][k];
        }
        cp4(dst, ent + (size_t)id * DIM + k);
    }
    cp_commit();
}

// Persistent: 296 blocks x 512 threads (16 warps). Warp w owns R columns
// [8w, 8w+8): B fragments (16 k-blocks x 2 regs) stationary per relation.
// Per tile: A = [h;ch] (16x128) in smem -> 16 tf32 MMAs accumulate
// Y(16x8) = A @ R_strip; epilogue dots Y rows with t/ct and reduces.
__global__ __launch_bounds__(THREADS, 2) void rescal_kernel(
    const void*  __restrict__ data,
    const float* __restrict__ ent,
    const float* __restrict__ rel,
    float*       __restrict__ out)
{
    __shared__ Buf   s_buf[2];
    __shared__ int   s_toff[N_REL];
    __shared__ int   s_ws[8], s_winc[8];
    __shared__ int   s_nt, s_is64;
    __shared__ int   st_r[MAXT], st_s[MAXT], st_n[MAXT];
    __shared__ int   s_ids[MAXT][TILE][4];
    __shared__ float wsum[TILE][16];
    __shared__ float s_part[16];
    __shared__ int   s_last;

    const int tid  = threadIdx.x;
    const int lane = tid & 31;
    const int wid  = tid >> 5;            // 0..15
    const int g    = lane >> 2;           // fragment group row (element)
    const int t4   = lane & 3;            // fragment k index

    if (tid == 0) s_is64 = detect_is64(data);

    // ---- tile-offset scan over g_cnt (shuffle scan, warps 0..7) ----
    int tc = 0, incl = 0;
    if (tid < 256) {
        tc = (tid < N_REL) ? (g_cnt[tid] + TILE - 1) / TILE : 0;
        int v = tc;
        #pragma unroll
        for (int o = 1; o < 32; o <<= 1) {
            int u = __shfl_up_sync(0xffffffffu, v, o);
            if (lane >= o) v += u;
        }
        if (lane == 31) s_ws[wid] = v;
        incl = v;
    }
    __syncthreads();
    if (wid == 0) {
        int x = (lane < 8) ? s_ws[lane] : 0;
        #pragma unroll
        for (int o = 1; o < 8; o <<= 1) {
            int u = __shfl_up_sync(0xffffffffu, x, o);
            if (lane >= o) x += u;
        }
        if (lane < 8) s_winc[lane] = x;
    }
    __syncthreads();
    if (tid < 256) {
        int base = (wid == 0) ? 0 : s_winc[wid - 1];
        incl += base;
        if (tid < N_REL) s_toff[tid] = incl - tc;  // exclusive prefix
        if (tid == N_REL - 1) s_nt = incl;
    }
    __syncthreads();

    const int nt  = s_nt;
    const int t0  = (int)((long long)blockIdx.x * nt / NBLOCKS);
    const int t1  = (int)((long long)(blockIdx.x + 1) * nt / NBLOCKS);
    const int ntb = t1 - t0;
    const int is64 = s_is64;

    // ---- per-tile metadata: binary search for relation ----
    if (tid < ntb) {
        int t = t0 + tid;
        int lo = 0, hi = N_REL;
        while (hi - lo > 1) {
            int m = (lo + hi) >> 1;
            if (s_toff[m] <= t) lo = m; else hi = m;
        }
        int s0 = (t - s_toff[lo]) * TILE;
        int nv = g_cnt[lo] - s0;
        st_r[tid] = lo;
        st_s[tid] = s0;
        st_n[tid] = (nv > TILE) ? TILE : nv;
    }
    __syncthreads();

    // ---- prefetch all entity ids for this block's tiles ----
    if (tid < ntb * TILE) {
        int tt = tid >> 3, e = tid & 7;
        int nv = st_n[tt];
        int b  = g_list[st_r[tt] * BATCH + st_s[tt] + ((e < nv) ? e : 0)];
        s_ids[tt][e][0] = read_idx(data, b * 5 + 0, is64, N_ENT);  // h
        s_ids[tt][e][1] = read_idx(data, b * 5 + 1, is64, N_ENT);  // t
        s_ids[tt][e][2] = read_idx(data, b * 5 + 3, is64, N_ENT);  // ch
        s_ids[tt][e][3] = read_idx(data, b * 5 + 4, is64, N_ENT);  // ct
    }
    __syncthreads();

    float2 Breg[16];                       // R strip frags: Breg[kb] = (b0, b1)
    int    cur_r = -1;
    float  blockAcc = 0.0f;                // carried on warps 0..3

    const int jglob = wid * 8 + g;         // this lane's B column
    if (ntb > 0) issue_gather(&s_buf[0], s_ids[0], ent, tid);

    for (int j = 0; j < ntb; j++) {
        if (j + 1 < ntb)
            issue_gather(&s_buf[(j + 1) & 1], s_ids[j + 1], ent, tid);

        const int r = st_r[j];
        if (r != cur_r) {                  // reload R strip (L2-hot, amortized)
            const float* Rp = rel + (size_t)r * (DIM * DIM);
            #pragma unroll
            for (int kb = 0; kb < 16; kb++) {
                Breg[kb].x = __ldg(Rp + (size_t)(kb * 8 + t4) * DIM + jglob);
                Breg[kb].y = __ldg(Rp + (size_t)(kb * 8 + t4 + 4) * DIM + jglob);
            }
            cur_r = r;
        }

        if (j + 1 < ntb) cp_wait1(); else cp_wait0();
        __syncthreads();                   // buf[j] ready; wsum free again

        const Buf* buf = &s_buf[j & 1];

        float c[4] = {0.0f, 0.0f, 0.0f, 0.0f};
        #pragma unroll
        for (int kb = 0; kb < 16; kb++) {
            int k0 = kb * 8 + t4;
            unsigned a0 = __float_as_uint(buf->A[g][k0]);
            unsigned a1 = __float_as_uint(buf->A[g + 8][k0]);
            unsigned a2 = __float_as_uint(buf->A[g][k0 + 4]);
            unsigned a3 = __float_as_uint(buf->A[g + 8][k0 + 4]);
            mma_tf32(c, a0, a1, a2, a3,
                     __float_as_uint(Breg[kb].x), __float_as_uint(Breg[kb].y));
        }

        // contrib(e=g) = c0*t[jc] + c1*t[jc+1] - c2*ct[jc] - c3*ct[jc+1]
        const int jc = wid * 8 + 2 * t4;
        float2 tp = *reinterpret_cast<const float2*>(&buf->T[g][jc]);
        float2 tn = *reinterpret_cast<const float2*>(&buf->T[g + 8][jc]);
        float contrib = c[0] * tp.x + c[1] * tp.y - c[2] * tn.x - c[3] * tn.y;
        contrib += __shfl_xor_sync(0xffffffffu, contrib, 1);
        contrib += __shfl_xor_sync(0xffffffffu, contrib, 2);
        if (t4 == 0) wsum[g][wid] = contrib;
        __syncthreads();                   // wsum complete

        // Warps 0..3 combine: e = wid*2 + (lane>>4), 16 lanes per element.
        if (wid < 4) {
            int e = wid * 2 + (lane >> 4);
            int w = lane & 15;
            float v = wsum[e][w];
            v += __shfl_xor_sync(0xffffffffu, v, 8);
            v += __shfl_xor_sync(0xffffffffu, v, 4);
            v += __shfl_xor_sync(0xffffffffu, v, 2);
            v += __shfl_xor_sync(0xffffffffu, v, 1);
            if (w == 0 && e < st_n[j]) {
                v += 1.0f;                 // + MARGIN
                if (v > 0.0f) blockAcc += v * (1.0f / BATCH);
            }
        }
    }

    // ---- block partial (blockAcc on lanes 0,16 of warps 0..3) ----
    __syncthreads();
    blockAcc += __shfl_xor_sync(0xffffffffu, blockAcc, 16);
    if (lane == 0) s_part[wid] = blockAcc;
    __syncthreads();
    if (tid == 0) {
        float total = s_part[0] + s_part[1] + s_part[2] + s_part[3];
        g_part[blockIdx.x] = total;
        __threadfence();
        unsigned int old = atomicAdd(&g_done, 1u);
        s_last = (old == NBLOCKS - 1) ? 1 : 0;
    }
    __syncthreads();
    if (s_last) {
        __threadfence();
        float v = (tid < NBLOCKS) ? g_part[tid] : 0.0f;
        #pragma unroll
        for (int o = 16; o; o >>= 1)
            v += __shfl_xor_sync(0xffffffffu, v, o);
        if (lane == 0) s_part[wid] = v;
        __syncthreads();
        if (wid == 0) {
            float x = (lane < 16) ? s_part[lane] : 0.0f;
            #pragma unroll
            for (int o = 8; o; o >>= 1)
                x += __shfl_xor_sync(0xffffffffu, x, o);
            if (lane == 0) out[0] = x;
        }
        // reset state for next graph replay
        if (tid < N_REL) g_cnt[tid] = 0;
        if (tid == 0)    g_done = 0u;
    }
}

extern "C" void kernel_launch(void* const* d_in, const int* in_sizes, int n_in,
                              void* d_out, int out_size) {
    const void*  data = d_in[0];
    const float* ent  = (const float*)d_in[1];
    const float* rel  = (const float*)d_in[2];
    float*       out  = (float*)d_out;

    build_kernel<<<(BATCH + THREADS - 1) / THREADS, THREADS>>>(data);
    rescal_kernel<<<NBLOCKS, THREADS>>>(data, ent, rel, out);
}